// round 13
// baseline (speedup 1.0000x reference)
#include <cuda_runtime.h>
#include <math.h>
#include <stdint.h>

#define R_ROIS   128
#define C_CH     512
#define HW       32
#define ROI      7
#define FLATK    25088      // 512*7*7
#define HID      4096
#define NLOC     84
#define NSCORE   21
#define SPLITS6  9
#define SPLITS7  9
#define HOUT     105        // 84 + 21
#define HSPLITS  128        // heads split-K count (K32 each)

// -------- scratch (static device globals; no runtime allocation) --------
__device__ float g_flat[R_ROIS * FLATK];            // tf32-valued
__device__ float g_fc6 [R_ROIS * HID];              // tf32-valued
__device__ float g_fc7 [R_ROIS * HID];              // fp32
__device__ float g_part[SPLITS6 * R_ROIS * HID];

// ============================ helpers ============================
__device__ __forceinline__ uint32_t smem_u32(const void* p) {
    uint32_t a;
    asm("{ .reg .u64 t; cvta.to.shared.u64 t, %1; cvt.u32.u64 %0, t; }" : "=r"(a) : "l"(p));
    return a;
}
__device__ __forceinline__ uint32_t f2tf32(float x) {
    uint32_t r; asm("cvt.rna.tf32.f32 %0, %1;" : "=r"(r) : "f"(x)); return r;
}
__device__ __forceinline__ void cp16(uint32_t dst, const void* src) {
    asm volatile("cp.async.cg.shared.global [%0], [%1], 16;" :: "r"(dst), "l"(src));
}
__device__ __forceinline__ void cp_commit() { asm volatile("cp.async.commit_group;"); }
__device__ __forceinline__ void cp_wait1()  { asm volatile("cp.async.wait_group 1;" ::: "memory"); }

__device__ __forceinline__ void mma8(float* d,
                                     uint32_t a0, uint32_t a1, uint32_t a2, uint32_t a3,
                                     uint32_t b0, uint32_t b1) {
    asm volatile(
        "mma.sync.aligned.m16n8k8.row.col.f32.tf32.tf32.f32 "
        "{%0,%1,%2,%3}, {%4,%5,%6,%7}, {%8,%9}, {%0,%1,%2,%3};"
        : "+f"(d[0]), "+f"(d[1]), "+f"(d[2]), "+f"(d[3])
        : "r"(a0), "r"(a1), "r"(a2), "r"(a3), "r"(b0), "r"(b1));
}
__device__ __forceinline__ void ldmA(uint32_t* r, uint32_t addr) {
    asm volatile("ldmatrix.sync.aligned.m8n8.x4.shared.b16 {%0,%1,%2,%3}, [%4];"
        : "=r"(r[0]), "=r"(r[1]), "=r"(r[2]), "=r"(r[3]) : "r"(addr));
}

// ============ SMEM ring geometry (bytes), 3 stages of K32; 105 KB/CTA -> 2 CTAs/SM ============
// A: 128 rows x 144 B pitch (128 B data; pitch-9x16B keeps ldmatrix conflict-free)
// B: 32 k-rows x 544 B pitch (136 floats; read banks 8t+g bijective -> conflict-free)
#define PAB         144
#define PBW         136
#define A_SZ        (128 * PAB)             // 18432
#define B_OFF       A_SZ
#define STAGE       (A_SZ + 32 * PBW * 4)   // 35840
#define NSTG        3
#define SMEM_TOT    (NSTG * STAGE)          // 107520

// ============================ RoI max pool (writes tf32-valued) ============================
__global__ void roi_pool_kernel(const float* __restrict__ x,
                                const float* __restrict__ rois,
                                const int*   __restrict__ roi_idx) {
    int i = blockIdx.x * blockDim.x + threadIdx.x;
    if (i >= R_ROIS * FLATK) return;
    int pw = i % ROI;
    int ph = (i / ROI) % ROI;
    int c  = (i / (ROI * ROI)) % C_CH;
    int r  = i / FLATK;

    float y1 = rois[r * 4 + 0];
    float x1 = rois[r * 4 + 1];
    float y2 = rois[r * 4 + 2];
    float x2 = rois[r * 4 + 3];

    float sw = rintf(x1 * 0.0625f);
    float sh = rintf(y1 * 0.0625f);
    float ew = rintf(x2 * 0.0625f);
    float eh = rintf(y2 * 0.0625f);
    float bin_w = fmaxf(ew - sw + 1.0f, 1.0f) * (1.0f / (float)ROI);
    float bin_h = fmaxf(eh - sh + 1.0f, 1.0f) * (1.0f / (float)ROI);

    int ws = (int)fminf(fmaxf(floorf((float)pw       * bin_w) + sw, 0.0f), 32.0f);
    int we = (int)fminf(fmaxf(ceilf ((float)(pw + 1) * bin_w) + sw, 0.0f), 32.0f);
    int hs = (int)fminf(fmaxf(floorf((float)ph       * bin_h) + sh, 0.0f), 32.0f);
    int he = (int)fminf(fmaxf(ceilf ((float)(ph + 1) * bin_h) + sh, 0.0f), 32.0f);

    int spanW = we - ws;
    float out = 0.0f;
    if (spanW > 0 && he > hs) {
        const float* f = x + ((size_t)roi_idx[r] * C_CH + c) * (HW * HW);
        float m = -3.402823466e38f;
        for (int h = hs; h < he; h++) {
            const float* row = f + h * HW + ws;
#pragma unroll
            for (int dw = 0; dw < 6; dw++)
                if (dw < spanW) m = fmaxf(m, row[dw]);
        }
        out = m;
    }
    g_flat[i] = __uint_as_float(f2tf32(out));   // A-side tf32 cvt done here
}

// ============================ tf32 mma.sync split-K GEMM ============================
// CTA tile M128 x N128 x K32; 256 threads = 8 warps (4M x 2N, warp tile 32x64).
// 3-stage cp.async ring, 2 CTAs/SM. A tf32-valued (ldmatrix), B raw fp32 (cvt at frag).

__device__ __forceinline__ void fill_stage(uint32_t stg, const float* __restrict__ A,
                                           int lda, const float* __restrict__ Wm,
                                           int n0, int kb, int tid) {
    // A: 128 rows x 128 B. thread -> row tid>>1, 64B half (tid&1), 4 cp16.
    {
        int r = tid >> 1;
        int h = tid & 1;
        const float* src = A + (size_t)r * lda + kb + h * 16;
        uint32_t dst = stg + (uint32_t)r * PAB + (uint32_t)h * 64;
#pragma unroll
        for (int q = 0; q < 4; q++) cp16(dst + q * 16, src + q * 4);
    }
    // B: 32 k-rows x 512 B. thread -> k tid>>3, 64B slice (tid&7), 4 cp16.
    {
        int k = tid >> 3;
        int s = tid & 7;
        const float* src = Wm + (size_t)(kb + k) * HID + n0 + s * 16;
        uint32_t dst = stg + B_OFF + (uint32_t)k * (PBW * 4) + (uint32_t)s * 64;
#pragma unroll
        for (int q = 0; q < 4; q++) cp16(dst + q * 16, src + q * 4);
    }
}

__global__ void __launch_bounds__(256, 2) gemm_tc_kernel(const float* __restrict__ Wm,
                                                         int which, int iters_per_split) {
    extern __shared__ float sm[];
    const float* A = which ? g_fc6 : g_flat;
    const int   Kdim = which ? HID : FLATK;
    const int totIters = Kdim / 32;

    const int tid  = threadIdx.x;
    const int lane = tid & 31, wid = tid >> 5;
    const int g    = lane >> 2, t = lane & 3;
    const int m0   = (wid & 3) * 32;
    const int nw   = (wid >> 2) * 64;
    const int n0   = blockIdx.x * 128;
    const int it0  = blockIdx.y * iters_per_split;
    const int nIt  = min(iters_per_split, totIters - it0);

    const uint32_t sb = smem_u32(sm);
    const uint32_t a_off = (uint32_t)(m0 + (lane & 15)) * PAB + ((lane >> 4) << 4);

    float acc[2][8][4];
#pragma unroll
    for (int mi = 0; mi < 2; mi++)
#pragma unroll
        for (int j = 0; j < 8; j++)
#pragma unroll
            for (int e = 0; e < 4; e++) acc[mi][j][e] = 0.0f;

    // prologue: fill stages 0..1
#pragma unroll
    for (int s = 0; s < NSTG - 1; s++) {
        if (s < nIt) fill_stage(sb + s * STAGE, A, Kdim, Wm, n0, (it0 + s) * 32, tid);
        cp_commit();
    }

    for (int it = 0; it < nIt; it++) {
        cp_wait1();            // stage `it` has landed
        __syncthreads();       // also: everyone done reading stage it-1 (slot of it+2)

        if (it + NSTG - 1 < nIt)
            fill_stage(sb + ((it + NSTG - 1) % NSTG) * STAGE, A, Kdim, Wm, n0,
                       (it0 + it + NSTG - 1) * 32, tid);
        cp_commit();

        const int slot = it % NSTG;
        const uint32_t aA = sb + slot * STAGE + a_off;
        const float*   Bs = sm + (slot * STAGE + B_OFF) / 4;

#pragma unroll
        for (int ks = 0; ks < 4; ks++) {
            uint32_t af[2][4];
#pragma unroll
            for (int mi = 0; mi < 2; mi++)
                ldmA(af[mi], aA + (uint32_t)(mi * 16 * PAB) + (uint32_t)(ks << 5));
            const float* brow0 = Bs + (ks * 8 + t) * PBW + nw + g;
            const float* brow1 = brow0 + 4 * PBW;
#pragma unroll
            for (int j = 0; j < 8; j++) {
                uint32_t b0 = f2tf32(brow0[j * 8]);
                uint32_t b1 = f2tf32(brow1[j * 8]);
#pragma unroll
                for (int mi = 0; mi < 2; mi++)
                    mma8(acc[mi][j], af[mi][0], af[mi][1], af[mi][2], af[mi][3], b0, b1);
            }
        }
    }

    // epilogue -> split-K partials
    float* P = g_part + (size_t)blockIdx.y * (R_ROIS * HID);
#pragma unroll
    for (int mi = 0; mi < 2; mi++) {
        int row = m0 + mi * 16 + g;
#pragma unroll
        for (int j = 0; j < 8; j++) {
            int col = n0 + nw + j * 8 + t * 2;
            *(float2*)&P[(size_t)row * HID + col]       = make_float2(acc[mi][j][0], acc[mi][j][1]);
            *(float2*)&P[(size_t)(row + 8) * HID + col] = make_float2(acc[mi][j][2], acc[mi][j][3]);
        }
    }
}

// ============================ split-K reduce + bias + relu ============================
__global__ void reduce_fc6_kernel(const float* __restrict__ b1) {
    int i = blockIdx.x * blockDim.x + threadIdx.x;
    if (i >= R_ROIS * HID) return;
    float s = 0.0f;
#pragma unroll
    for (int q = 0; q < SPLITS6; q++) s += g_part[(size_t)q * R_ROIS * HID + i];
    s += b1[i & (HID - 1)];
    g_fc6[i] = __uint_as_float(f2tf32(fmaxf(s, 0.0f)));   // tf32-valued (fc7 A side)
}
__global__ void reduce_fc7_kernel(const float* __restrict__ b2) {
    int i = blockIdx.x * blockDim.x + threadIdx.x;
    if (i >= R_ROIS * HID) return;
    float s = 0.0f;
#pragma unroll
    for (int q = 0; q < SPLITS7; q++) s += g_part[(size_t)q * R_ROIS * HID + i];
    s += b2[i & (HID - 1)];
    g_fc7[i] = fmaxf(s, 0.0f);
}

// ============================ heads: split-K mini-GEMM ============================
__global__ void __launch_bounds__(512) heads_gemm_kernel(const float* __restrict__ Wl,
                                                         const float* __restrict__ Ws) {
    __shared__ float As[128 * 33];
    __shared__ float Wt[32 * 106];
    const int s   = blockIdx.x;
    const int k0  = s * 32;
    const int tid = threadIdx.x;

    for (int i = tid; i < 128 * 32; i += 512) {
        int r = i >> 5, k = i & 31;
        As[r * 33 + k] = g_fc7[(size_t)r * HID + k0 + k];
    }
    for (int i = tid; i < 32 * HOUT; i += 512) {
        int k = i / HOUT, n = i % HOUT;
        Wt[k * 106 + n] = (n < NLOC) ? Wl[(size_t)(k0 + k) * NLOC + n]
                                     : Ws[(size_t)(k0 + k) * NSCORE + (n - NLOC)];
    }
    __syncthreads();

    int rg = tid >> 4;
    int ng = tid & 15;
    if (ng < 15) {
        float acc[4][7];
#pragma unroll
        for (int rr = 0; rr < 4; rr++)
#pragma unroll
            for (int jj = 0; jj < 7; jj++) acc[rr][jj] = 0.0f;

        for (int k = 0; k < 32; k++) {
            float w[7], a[4];
#pragma unroll
            for (int jj = 0; jj < 7; jj++) w[jj] = Wt[k * 106 + ng * 7 + jj];
#pragma unroll
            for (int rr = 0; rr < 4; rr++) a[rr] = As[(rg * 4 + rr) * 33 + k];
#pragma unroll
            for (int rr = 0; rr < 4; rr++)
#pragma unroll
                for (int jj = 0; jj < 7; jj++)
                    acc[rr][jj] = fmaf(a[rr], w[jj], acc[rr][jj]);
        }
        float* P = g_part + (size_t)s * (R_ROIS * HOUT);
#pragma unroll
        for (int rr = 0; rr < 4; rr++)
#pragma unroll
            for (int jj = 0; jj < 7; jj++)
                P[(rg * 4 + rr) * HOUT + ng * 7 + jj] = acc[rr][jj];
    }
}

__global__ void heads_reduce_kernel(const float* __restrict__ bl,
                                    const float* __restrict__ bs,
                                    float* __restrict__ out) {
    int i = blockIdx.x * blockDim.x + threadIdx.x;
    if (i >= R_ROIS * HOUT) return;
    int r = i / HOUT, n = i % HOUT;
    float s = 0.0f;
    for (int q = 0; q < HSPLITS; q++) s += g_part[(size_t)q * (R_ROIS * HOUT) + i];
    if (n < NLOC) {
        out[(size_t)r * NLOC + n] = s + bl[n];
    } else {
        out[(size_t)R_ROIS * NLOC + (size_t)r * NSCORE + (n - NLOC)] = s + bs[n - NLOC];
    }
}

// ============================ launch ============================
extern "C" void kernel_launch(void* const* d_in, const int* in_sizes, int n_in,
                              void* d_out, int out_size) {
    const float* x    = (const float*)d_in[0];
    const float* rois = (const float*)d_in[1];
    const int*   idx  = (const int*)  d_in[2];
    const float* W1   = (const float*)d_in[3];
    const float* b1   = (const float*)d_in[4];
    const float* W2   = (const float*)d_in[5];
    const float* b2   = (const float*)d_in[6];
    const float* Wl   = (const float*)d_in[7];
    const float* bl   = (const float*)d_in[8];
    const float* Ws   = (const float*)d_in[9];
    const float* bs   = (const float*)d_in[10];
    float* out = (float*)d_out;

    cudaFuncSetAttribute(gemm_tc_kernel, cudaFuncAttributeMaxDynamicSharedMemorySize, SMEM_TOT);

    // 1) RoI pool -> g_flat [128, 25088] (tf32-valued)
    roi_pool_kernel<<<(R_ROIS * FLATK + 255) / 256, 256>>>(x, rois, idx);

    // 2) fc6: K=25088 -> 784 K32-iters, 9 splits of <=88; grid 32 x 9 = 288 CTAs (2/SM)
    gemm_tc_kernel<<<dim3(HID / 128, SPLITS6), 256, SMEM_TOT>>>(W1, 0, 88);
    reduce_fc6_kernel<<<(R_ROIS * HID + 255) / 256, 256>>>(b1);

    // 3) fc7: K=4096 -> 128 K32-iters, 9 splits of <=15; grid 32 x 9 = 288 CTAs
    gemm_tc_kernel<<<dim3(HID / 128, SPLITS7), 256, SMEM_TOT>>>(W2, 1, 15);
    reduce_fc7_kernel<<<(R_ROIS * HID + 255) / 256, 256>>>(b2);

    // 4) heads: 128-split mini-GEMM + reduce -> out = [locs 128*84 | scores 128*21]
    heads_gemm_kernel<<<HSPLITS, 512>>>(Wl, Ws);
    heads_reduce_kernel<<<(R_ROIS * HOUT + 255) / 256, 256>>>(bl, bs, out);
}

// round 14
// speedup vs baseline: 1.4873x; 1.4873x over previous
#include <cuda_runtime.h>
#include <math.h>
#include <stdint.h>

#define R_ROIS   128
#define C_CH     512
#define HW       32
#define ROI      7
#define FLATK    25088      // 512*7*7
#define HID      4096
#define NLOC     84
#define NSCORE   21
#define SPLITS6  9
#define SPLITS7  8
#define HOUT     105        // 84 + 21
#define HSPLITS  128        // heads split-K count (K32 each)

// -------- scratch (static device globals; no runtime allocation) --------
__device__ float g_flat[R_ROIS * FLATK];            // tf32-valued
__device__ float g_fc6 [R_ROIS * HID];              // tf32-valued
__device__ float g_fc7 [R_ROIS * HID];              // fp32
__device__ float g_part[SPLITS6 * R_ROIS * HID];

// ============================ helpers ============================
__device__ __forceinline__ uint32_t smem_u32(const void* p) {
    uint32_t a;
    asm("{ .reg .u64 t; cvta.to.shared.u64 t, %1; cvt.u32.u64 %0, t; }" : "=r"(a) : "l"(p));
    return a;
}
__device__ __forceinline__ uint32_t f2tf32(float x) {
    uint32_t r; asm("cvt.rna.tf32.f32 %0, %1;" : "=r"(r) : "f"(x)); return r;
}
__device__ __forceinline__ void cp16(uint32_t dst, const void* src) {
    asm volatile("cp.async.cg.shared.global [%0], [%1], 16;" :: "r"(dst), "l"(src));
}
__device__ __forceinline__ void cp_commit() { asm volatile("cp.async.commit_group;"); }
__device__ __forceinline__ void cp_wait1()  { asm volatile("cp.async.wait_group 1;" ::: "memory"); }

__device__ __forceinline__ void mma8(float* d,
                                     uint32_t a0, uint32_t a1, uint32_t a2, uint32_t a3,
                                     uint32_t b0, uint32_t b1) {
    asm volatile(
        "mma.sync.aligned.m16n8k8.row.col.f32.tf32.tf32.f32 "
        "{%0,%1,%2,%3}, {%4,%5,%6,%7}, {%8,%9}, {%0,%1,%2,%3};"
        : "+f"(d[0]), "+f"(d[1]), "+f"(d[2]), "+f"(d[3])
        : "r"(a0), "r"(a1), "r"(a2), "r"(a3), "r"(b0), "r"(b1));
}
__device__ __forceinline__ void ldmA(uint32_t* r, uint32_t addr) {
    asm volatile("ldmatrix.sync.aligned.m8n8.x4.shared.b16 {%0,%1,%2,%3}, [%4];"
        : "=r"(r[0]), "=r"(r[1]), "=r"(r[2]), "=r"(r[3]) : "r"(addr));
}

// ============ SMEM: 2 stages of K64, M128 x N256 ============
// A: 128 rows x 272 B pitch (256 B data; 17x16B odd pitch -> ldmatrix conflict-free)
// B: 64 k-rows x 1056 B pitch (264 floats; frag banks 8t+g bijective -> conflict-free)
#define PAB         272
#define PBB         1056
#define PBW         264
#define A_SZ        (128 * PAB)             // 34816
#define B_OFF       A_SZ
#define STAGE       (A_SZ + 64 * PBB)       // 102400
#define SMEM_TOT    (2 * STAGE)             // 204800

// ============================ RoI max pool (writes tf32-valued) ============================
__global__ void roi_pool_kernel(const float* __restrict__ x,
                                const float* __restrict__ rois,
                                const int*   __restrict__ roi_idx) {
    int i = blockIdx.x * blockDim.x + threadIdx.x;
    if (i >= R_ROIS * FLATK) return;
    int pw = i % ROI;
    int ph = (i / ROI) % ROI;
    int c  = (i / (ROI * ROI)) % C_CH;
    int r  = i / FLATK;

    float y1 = rois[r * 4 + 0];
    float x1 = rois[r * 4 + 1];
    float y2 = rois[r * 4 + 2];
    float x2 = rois[r * 4 + 3];

    float sw = rintf(x1 * 0.0625f);
    float sh = rintf(y1 * 0.0625f);
    float ew = rintf(x2 * 0.0625f);
    float eh = rintf(y2 * 0.0625f);
    float bin_w = fmaxf(ew - sw + 1.0f, 1.0f) * (1.0f / (float)ROI);
    float bin_h = fmaxf(eh - sh + 1.0f, 1.0f) * (1.0f / (float)ROI);

    int ws = (int)fminf(fmaxf(floorf((float)pw       * bin_w) + sw, 0.0f), 32.0f);
    int we = (int)fminf(fmaxf(ceilf ((float)(pw + 1) * bin_w) + sw, 0.0f), 32.0f);
    int hs = (int)fminf(fmaxf(floorf((float)ph       * bin_h) + sh, 0.0f), 32.0f);
    int he = (int)fminf(fmaxf(ceilf ((float)(ph + 1) * bin_h) + sh, 0.0f), 32.0f);

    int spanW = we - ws;
    float out = 0.0f;
    if (spanW > 0 && he > hs) {
        const float* f = x + ((size_t)roi_idx[r] * C_CH + c) * (HW * HW);
        float m = -3.402823466e38f;
        for (int h = hs; h < he; h++) {
            const float* row = f + h * HW + ws;
#pragma unroll
            for (int dw = 0; dw < 6; dw++)
                if (dw < spanW) m = fmaxf(m, row[dw]);
        }
        out = m;
    }
    g_flat[i] = __uint_as_float(f2tf32(out));   // A-side tf32 cvt done here
}

// ============================ tf32 mma.sync split-K GEMM ============================
// CTA tile M128 x N256 x K64; 256 threads = 8 warps (2M x 4N), warp tile M64 x N64.
// 2-stage cp.async ring with wavefront-perfect fills (each cp16 instr: 32 lanes
// cover 512 contiguous bytes = 4 full 128B wavefronts).

__device__ __forceinline__ void fill_stage(uint32_t stg, const float* __restrict__ A,
                                           int lda, const float* __restrict__ Wm,
                                           int n0, int kb, int tid) {
    // A: 128 rows x 256 B = 2048 16B-chunks; chunk c: row=c>>4, off=c&15.
#pragma unroll
    for (int q = 0; q < 8; q++) {
        int c   = tid + q * 256;
        int row = c >> 4;
        int off = c & 15;
        cp16(stg + (uint32_t)row * PAB + (uint32_t)off * 16,
             A + (size_t)row * lda + kb + off * 4);
    }
    // B: 64 rows x 1024 B = 4096 chunks; chunk c: row=c>>6, off=c&63.
#pragma unroll
    for (int q = 0; q < 16; q++) {
        int c   = tid + q * 256;
        int row = c >> 6;
        int off = c & 63;
        cp16(stg + B_OFF + (uint32_t)row * PBB + (uint32_t)off * 16,
             Wm + (size_t)(kb + row) * HID + n0 + off * 4);
    }
}

__global__ void __launch_bounds__(256, 1) gemm_tc_kernel(const float* __restrict__ Wm,
                                                         int which, int iters_per_split) {
    extern __shared__ float sm[];
    const float* A = which ? g_fc6 : g_flat;
    const int   Kdim = which ? HID : FLATK;
    const int totIters = Kdim / 64;

    const int tid  = threadIdx.x;
    const int lane = tid & 31, wid = tid >> 5;
    const int g    = lane >> 2, t = lane & 3;
    const int m0   = (wid & 1) * 64;
    const int nw   = (wid >> 1) * 64;
    const int n0   = blockIdx.x * 256;
    const int it0  = blockIdx.y * iters_per_split;
    const int nIt  = min(iters_per_split, totIters - it0);

    const uint32_t sb = smem_u32(sm);
    const uint32_t a_off = (uint32_t)(m0 + (lane & 15)) * PAB + ((lane >> 4) << 4);

    float acc[4][8][4];
#pragma unroll
    for (int mi = 0; mi < 4; mi++)
#pragma unroll
        for (int j = 0; j < 8; j++)
#pragma unroll
            for (int e = 0; e < 4; e++) acc[mi][j][e] = 0.0f;

    // prologue: fill both stages
    if (0 < nIt) fill_stage(sb, A, Kdim, Wm, n0, it0 * 64, tid);
    cp_commit();
    if (1 < nIt) fill_stage(sb + STAGE, A, Kdim, Wm, n0, (it0 + 1) * 64, tid);
    cp_commit();

    for (int it = 0; it < nIt; it++) {
        cp_wait1();            // stage `it` has landed
        __syncthreads();

        const int slot = it & 1;
        const uint32_t aA = sb + slot * STAGE + a_off;
        const float*   Bs = sm + (slot * STAGE + B_OFF) / 4;

#pragma unroll
        for (int ks = 0; ks < 8; ks++) {
            uint32_t af[4][4];
#pragma unroll
            for (int mi = 0; mi < 4; mi++)
                ldmA(af[mi], aA + (uint32_t)(mi * 16 * PAB) + (uint32_t)(ks * 32));
            const float* brow0 = Bs + (ks * 8 + t) * PBW + nw + g;
            const float* brow1 = brow0 + 4 * PBW;
#pragma unroll
            for (int j = 0; j < 8; j++) {
                uint32_t b0 = f2tf32(brow0[j * 8]);
                uint32_t b1 = f2tf32(brow1[j * 8]);
#pragma unroll
                for (int mi = 0; mi < 4; mi++)
                    mma8(acc[mi][j], af[mi][0], af[mi][1], af[mi][2], af[mi][3], b0, b1);
            }
        }
        __syncthreads();       // all warps done reading `slot` before refill

        if (it + 2 < nIt)
            fill_stage(sb + slot * STAGE, A, Kdim, Wm, n0, (it0 + it + 2) * 64, tid);
        cp_commit();
    }

    // epilogue -> split-K partials
    float* P = g_part + (size_t)blockIdx.y * (R_ROIS * HID);
#pragma unroll
    for (int mi = 0; mi < 4; mi++) {
        int row = m0 + mi * 16 + g;
#pragma unroll
        for (int j = 0; j < 8; j++) {
            int col = n0 + nw + j * 8 + t * 2;
            *(float2*)&P[(size_t)row * HID + col]       = make_float2(acc[mi][j][0], acc[mi][j][1]);
            *(float2*)&P[(size_t)(row + 8) * HID + col] = make_float2(acc[mi][j][2], acc[mi][j][3]);
        }
    }
}

// ============================ split-K reduce + bias + relu ============================
__global__ void reduce_fc6_kernel(const float* __restrict__ b1) {
    int i = blockIdx.x * blockDim.x + threadIdx.x;
    if (i >= R_ROIS * HID) return;
    float s = 0.0f;
#pragma unroll
    for (int q = 0; q < SPLITS6; q++) s += g_part[(size_t)q * R_ROIS * HID + i];
    s += b1[i & (HID - 1)];
    g_fc6[i] = __uint_as_float(f2tf32(fmaxf(s, 0.0f)));   // tf32-valued (fc7 A side)
}
__global__ void reduce_fc7_kernel(const float* __restrict__ b2) {
    int i = blockIdx.x * blockDim.x + threadIdx.x;
    if (i >= R_ROIS * HID) return;
    float s = 0.0f;
#pragma unroll
    for (int q = 0; q < SPLITS7; q++) s += g_part[(size_t)q * R_ROIS * HID + i];
    s += b2[i & (HID - 1)];
    g_fc7[i] = fmaxf(s, 0.0f);
}

// ============================ heads: split-K mini-GEMM ============================
__global__ void __launch_bounds__(512) heads_gemm_kernel(const float* __restrict__ Wl,
                                                         const float* __restrict__ Ws) {
    __shared__ float As[128 * 33];
    __shared__ float Wt[32 * 106];
    const int s   = blockIdx.x;
    const int k0  = s * 32;
    const int tid = threadIdx.x;

    for (int i = tid; i < 128 * 32; i += 512) {
        int r = i >> 5, k = i & 31;
        As[r * 33 + k] = g_fc7[(size_t)r * HID + k0 + k];
    }
    for (int i = tid; i < 32 * HOUT; i += 512) {
        int k = i / HOUT, n = i % HOUT;
        Wt[k * 106 + n] = (n < NLOC) ? Wl[(size_t)(k0 + k) * NLOC + n]
                                     : Ws[(size_t)(k0 + k) * NSCORE + (n - NLOC)];
    }
    __syncthreads();

    int rg = tid >> 4;
    int ng = tid & 15;
    if (ng < 15) {
        float acc[4][7];
#pragma unroll
        for (int rr = 0; rr < 4; rr++)
#pragma unroll
            for (int jj = 0; jj < 7; jj++) acc[rr][jj] = 0.0f;

        for (int k = 0; k < 32; k++) {
            float w[7], a[4];
#pragma unroll
            for (int jj = 0; jj < 7; jj++) w[jj] = Wt[k * 106 + ng * 7 + jj];
#pragma unroll
            for (int rr = 0; rr < 4; rr++) a[rr] = As[(rg * 4 + rr) * 33 + k];
#pragma unroll
            for (int rr = 0; rr < 4; rr++)
#pragma unroll
                for (int jj = 0; jj < 7; jj++)
                    acc[rr][jj] = fmaf(a[rr], w[jj], acc[rr][jj]);
        }
        float* P = g_part + (size_t)s * (R_ROIS * HOUT);
#pragma unroll
        for (int rr = 0; rr < 4; rr++)
#pragma unroll
            for (int jj = 0; jj < 7; jj++)
                P[(rg * 4 + rr) * HOUT + ng * 7 + jj] = acc[rr][jj];
    }
}

__global__ void heads_reduce_kernel(const float* __restrict__ bl,
                                    const float* __restrict__ bs,
                                    float* __restrict__ out) {
    int i = blockIdx.x * blockDim.x + threadIdx.x;
    if (i >= R_ROIS * HOUT) return;
    int r = i / HOUT, n = i % HOUT;
    float s = 0.0f;
    for (int q = 0; q < HSPLITS; q++) s += g_part[(size_t)q * (R_ROIS * HOUT) + i];
    if (n < NLOC) {
        out[(size_t)r * NLOC + n] = s + bl[n];
    } else {
        out[(size_t)R_ROIS * NLOC + (size_t)r * NSCORE + (n - NLOC)] = s + bs[n - NLOC];
    }
}

// ============================ launch ============================
extern "C" void kernel_launch(void* const* d_in, const int* in_sizes, int n_in,
                              void* d_out, int out_size) {
    const float* x    = (const float*)d_in[0];
    const float* rois = (const float*)d_in[1];
    const int*   idx  = (const int*)  d_in[2];
    const float* W1   = (const float*)d_in[3];
    const float* b1   = (const float*)d_in[4];
    const float* W2   = (const float*)d_in[5];
    const float* b2   = (const float*)d_in[6];
    const float* Wl   = (const float*)d_in[7];
    const float* bl   = (const float*)d_in[8];
    const float* Ws   = (const float*)d_in[9];
    const float* bs   = (const float*)d_in[10];
    float* out = (float*)d_out;

    cudaFuncSetAttribute(gemm_tc_kernel, cudaFuncAttributeMaxDynamicSharedMemorySize, SMEM_TOT);

    // 1) RoI pool -> g_flat [128, 25088] (tf32-valued)
    roi_pool_kernel<<<(R_ROIS * FLATK + 255) / 256, 256>>>(x, rois, idx);

    // 2) fc6: K=25088 -> 392 K64-iters, 9 splits of <=44; grid 16 x 9 = 144 CTAs
    gemm_tc_kernel<<<dim3(HID / 256, SPLITS6), 256, SMEM_TOT>>>(W1, 0, 44);
    reduce_fc6_kernel<<<(R_ROIS * HID + 255) / 256, 256>>>(b1);

    // 3) fc7: K=4096 -> 64 K64-iters, 8 splits of 8; grid 16 x 8 = 128 CTAs
    gemm_tc_kernel<<<dim3(HID / 256, SPLITS7), 256, SMEM_TOT>>>(W2, 1, 8);
    reduce_fc7_kernel<<<(R_ROIS * HID + 255) / 256, 256>>>(b2);

    // 4) heads: 128-split mini-GEMM + reduce -> out = [locs 128*84 | scores 128*21]
    heads_gemm_kernel<<<HSPLITS, 512>>>(Wl, Ws);
    heads_reduce_kernel<<<(R_ROIS * HOUT + 255) / 256, 256>>>(bl, bs, out);
}